// round 6
// baseline (speedup 1.0000x reference)
#include <cuda_runtime.h>
#include <cstdint>

// ============================================================================
// Y[500000,256] = X @ W via fallback-HMMA tf32 mma.sync (tcgen05 unavailable
// at the harness's plain sm_103 PTX target).
//
// R5 change: 512 threads / 16 warps (4 per SMSP) to hide LDS->HMMA latency,
// warp tile 32x32 (4 m-groups x 4 n-groups), acc = 32 regs/thread.
// Everything else kept: tf32-rna rounding (rel_err ~3e-4), CTA pairing for
// X L2 reuse, fragment-order smem (conflict-free LDS.128/LDS.64), double-
// buffered 64-K chunks, streaming Y stores.
// ============================================================================

#define D_DIM    256
#define N_HALF   128
#define M_TILE   128
#define K_CHUNK  64
#define NCHUNKS  4
#define NROWS_T  500000L
#define NTILES_T 3907        // ceil(500000/128)
#define NPAIRS   76
#define NCTA     152
#define NTHREADS 512

// smem layout (bytes):  B frags [16 nt][32 ks][32 lane][2 f32] = 131072
//                       A frags 2 stages x [8 mt][8 ks][32 lane][4 f32] = 65536
#define SB_B       0
#define SB_A       131072
#define A_STAGE_B  32768
#define SMEM_TOTAL (SB_A + 2 * A_STAGE_B)   // 196608

__device__ __align__(16) float g_Wt[D_DIM * D_DIM];  // g_Wt[n*256+k] = W[k][n]

// ---------------------------------------------------------------------------
__device__ __forceinline__ uint32_t smem_u32(const void* p) {
    uint32_t a;
    asm("{ .reg .u64 t; cvta.to.shared.u64 t, %1; cvt.u32.u64 %0, t; }"
        : "=r"(a) : "l"(p));
    return a;
}
__device__ __forceinline__ float to_tf32(float x) {
    float r; asm("cvt.rna.tf32.f32 %0, %1;" : "=f"(r) : "f"(x)); return r;
}
__device__ __forceinline__ void sts32(uint32_t a, float v) {
    asm volatile("st.shared.f32 [%0], %1;" :: "r"(a), "f"(v) : "memory");
}
__device__ __forceinline__ uint4 lds128(uint32_t a) {
    uint4 v;
    asm volatile("ld.shared.v4.b32 {%0,%1,%2,%3}, [%4];"
                 : "=r"(v.x), "=r"(v.y), "=r"(v.z), "=r"(v.w) : "r"(a));
    return v;
}
__device__ __forceinline__ uint2 lds64(uint32_t a) {
    uint2 v;
    asm volatile("ld.shared.v2.b32 {%0,%1}, [%2];" : "=r"(v.x), "=r"(v.y) : "r"(a));
    return v;
}
__device__ __forceinline__ void stg64_cs(float* p, float a, float b) {
    asm volatile("st.global.cs.v2.f32 [%0], {%1,%2};"
                 :: "l"(p), "f"(a), "f"(b) : "memory");
}
// D = A(16x8,row) * B(8x8,col) + D,  tf32 inputs (pre-rounded), f32 accum
__device__ __forceinline__ void mma_tf32(float* c, uint4 a, uint2 b) {
    asm volatile(
        "mma.sync.aligned.m16n8k8.row.col.f32.tf32.tf32.f32 "
        "{%0,%1,%2,%3}, {%4,%5,%6,%7}, {%8,%9}, {%0,%1,%2,%3};"
        : "+f"(c[0]), "+f"(c[1]), "+f"(c[2]), "+f"(c[3])
        : "r"(a.x), "r"(a.y), "r"(a.z), "r"(a.w), "r"(b.x), "r"(b.y));
}

// ---------------------------------------------------------------------------
// W build
// ---------------------------------------------------------------------------
__global__ void build_zero_kernel() {
    g_Wt[blockIdx.x * 256 + threadIdx.x] = 0.0f;
}
__global__ void build_scatter_kernel(const float* __restrict__ w,
                                     const int* __restrict__ rows,
                                     const int* __restrict__ cols, int nnz) {
    int i = blockIdx.x * 256 + threadIdx.x;
    if (i < nnz) g_Wt[cols[i] * D_DIM + rows[i]] = to_tf32(w[i]);
}

// ---------------------------------------------------------------------------
// Persistent GEMM
// ---------------------------------------------------------------------------
__global__ void __launch_bounds__(NTHREADS, 1)
dag_gemm_kernel(const float* __restrict__ X, float* __restrict__ Y) {
    extern __shared__ char smem[];
    const uint32_t sb = smem_u32(smem);
    const int tid  = threadIdx.x;
    const int w    = tid >> 5;
    const int lane = tid & 31;
    const int g    = lane >> 2;      // groupID
    const int tig  = lane & 3;       // thread-in-group
    const int cta  = blockIdx.x;
    const int h    = cta & 1;        // N-half
    const int pair = cta >> 1;
    const int ntiles = (NTILES_T - pair + NPAIRS - 1) / NPAIRS;

    // ---- pack B-half into fragment order (once) -------------------------
    // B_frag[nt(16)][ksg(32)][lane(32)][j(2)]:
    //   value = W[k][n] = g_Wt[n*256+k],
    //   n = h*128 + nt*8 + (lane>>2),  k = ksg*8 + (lane&3) + j*4
    for (int i = 0; i < 32; i++) {
        int fid  = tid + (i << 9);          // 0..16383 over (nt,ks,lane)
        int ln   = fid & 31;
        int ks   = (fid >> 5) & 31;
        int nt   = fid >> 10;               // 0..15
        int n    = h * N_HALF + nt * 8 + (ln >> 2);
        int k0   = ks * 8 + (ln & 3);
        float b0 = g_Wt[n * D_DIM + k0];
        float b1 = g_Wt[n * D_DIM + k0 + 4];
        uint32_t a = sb + SB_B + (uint32_t)fid * 8;
        asm volatile("st.shared.v2.f32 [%0], {%1,%2};" :: "r"(a), "f"(b0), "f"(b1)
                     : "memory");
    }

    // producer mapping: row r = tid>>2, col quarter hc = tid&3 (16 cols each)
    const int pr  = tid >> 2;
    const int hc  = tid & 3;
    const int nchunks = ntiles * NCHUNKS;

    // warp tiling: 4 m-groups x 4 n-groups, warp tile 32x32
    const int mtg0 = (w & 3) * 2;           // first of 2 mtiles (of 8)
    const int ng   = (w >> 2);              // 0..3
    float acc[2][4][4];
    #pragma unroll
    for (int mt = 0; mt < 2; mt++)
        #pragma unroll
        for (int nt = 0; nt < 4; nt++)
            #pragma unroll
            for (int q = 0; q < 4; q++) acc[mt][nt][q] = 0.0f;

    // A-frag STS addresses for this thread's 4 float4s (row pr, cols hc*16+4q):
    //   rl=pr&15, mt=pr>>4; kk: ks=kk>>3, regbit1=(kk>>2)&1
    //   lane_e = ((rl&7)<<2)|e, reg = (rl>>3) | (regbit1<<1)
    uint32_t a_sts[4];
    {
        int mt = pr >> 4, rl = pr & 15;
        #pragma unroll
        for (int q = 0; q < 4; q++) {
            int kk  = hc * 16 + q * 4;
            int reg = (rl >> 3) | (((kk >> 2) & 1) << 1);
            int ln0 = (rl & 7) << 2;
            a_sts[q] = (uint32_t)((((mt * 8 + (kk >> 3)) * 32 + ln0) * 4 + reg) * 4);
        }
    }

    float4 v[4];
    // ---- prologue: load+convert+store chunk 0 ---------------------------
    {
        long m0 = (long)pair * M_TILE;
        long grow = m0 + pr;
        const float4* src = reinterpret_cast<const float4*>(
            X + grow * D_DIM + hc * 16);
        #pragma unroll
        for (int q = 0; q < 4; q++)
            v[q] = (grow < NROWS_T) ? src[q] : make_float4(0.f, 0.f, 0.f, 0.f);
        uint32_t ab = sb + SB_A;
        #pragma unroll
        for (int q = 0; q < 4; q++) {
            sts32(ab + a_sts[q],      to_tf32(v[q].x));
            sts32(ab + a_sts[q] + 16, to_tf32(v[q].y));
            sts32(ab + a_sts[q] + 32, to_tf32(v[q].z));
            sts32(ab + a_sts[q] + 48, to_tf32(v[q].w));
        }
    }

    for (int cg = 0; cg < nchunks; cg++) {
        __syncthreads();   // chunk cg resident in buffer cg&1

        const int j  = cg >> 2;       // tile
        const int ch = cg & 3;        // k-chunk
        const long m0 = (long)(pair + (long)j * NPAIRS) * M_TILE;

        // prefetch next chunk into registers (latency hidden by compute)
        if (cg + 1 < nchunks) {
            const int jn  = (cg + 1) >> 2;
            const int chn = (cg + 1) & 3;
            long m0n = (long)(pair + (long)jn * NPAIRS) * M_TILE;
            long grow = m0n + pr;
            const float4* src = reinterpret_cast<const float4*>(
                X + grow * D_DIM + chn * K_CHUNK + hc * 16);
            #pragma unroll
            for (int q = 0; q < 4; q++)
                v[q] = (grow < NROWS_T) ? src[q] : make_float4(0.f, 0.f, 0.f, 0.f);
        }

        // ---- compute chunk from smem buffer -----------------------------
        {
            const uint32_t ab = sb + SB_A + (uint32_t)(cg & 1) * A_STAGE_B;
            const uint32_t bb = sb + SB_B;
            #pragma unroll
            for (int ks = 0; ks < 8; ks++) {
                const int ksg = ch * 8 + ks;
                uint4 a0 = lds128(ab + (uint32_t)((((mtg0    ) * 8 + ks) * 32 + lane) * 16));
                uint4 a1 = lds128(ab + (uint32_t)((((mtg0 + 1) * 8 + ks) * 32 + lane) * 16));
                uint2 bfr[4];
                #pragma unroll
                for (int nt = 0; nt < 4; nt++)
                    bfr[nt] = lds64(bb + (uint32_t)((((ng * 4 + nt) * 32 + ksg) * 32 + lane) * 8));
                #pragma unroll
                for (int nt = 0; nt < 4; nt++) {
                    mma_tf32(acc[0][nt], a0, bfr[nt]);
                    mma_tf32(acc[1][nt], a1, bfr[nt]);
                }
            }
        }

        // ---- epilogue on last chunk of tile -----------------------------
        if (ch == 3) {
            const long mw = m0 + (long)(w & 3) * 32;
            const int  nb = h * N_HALF + ng * 32;
            #pragma unroll
            for (int mt = 0; mt < 2; mt++) {
                long r0 = mw + mt * 16 + g;
                long r1 = r0 + 8;
                #pragma unroll
                for (int nt = 0; nt < 4; nt++) {
                    int c0 = nb + nt * 8 + tig * 2;
                    if (r0 < NROWS_T)
                        stg64_cs(Y + r0 * D_DIM + c0, acc[mt][nt][0], acc[mt][nt][1]);
                    if (r1 < NROWS_T)
                        stg64_cs(Y + r1 * D_DIM + c0, acc[mt][nt][2], acc[mt][nt][3]);
                    #pragma unroll
                    for (int q = 0; q < 4; q++) acc[mt][nt][q] = 0.0f;
                }
            }
        }

        // ---- convert + store prefetched chunk into other buffer ---------
        if (cg + 1 < nchunks) {
            uint32_t ab = sb + SB_A + (uint32_t)((cg + 1) & 1) * A_STAGE_B;
            #pragma unroll
            for (int q = 0; q < 4; q++) {
                sts32(ab + a_sts[q],      to_tf32(v[q].x));
                sts32(ab + a_sts[q] + 16, to_tf32(v[q].y));
                sts32(ab + a_sts[q] + 32, to_tf32(v[q].z));
                sts32(ab + a_sts[q] + 48, to_tf32(v[q].w));
            }
        }
    }
}

// ---------------------------------------------------------------------------
extern "C" void kernel_launch(void* const* d_in, const int* in_sizes, int n_in,
                              void* d_out, int out_size) {
    const float* X    = (const float*)d_in[0];
    const float* wv   = (const float*)d_in[1];
    const int*   rows = (const int*)d_in[2];
    const int*   cols = (const int*)d_in[3];
    const int nnz = in_sizes[1];

    build_zero_kernel<<<D_DIM * D_DIM / 256, 256>>>();
    build_scatter_kernel<<<(nnz + 255) / 256, 256>>>(wv, rows, cols, nnz);

    cudaFuncSetAttribute(dag_gemm_kernel,
                         cudaFuncAttributeMaxDynamicSharedMemorySize, SMEM_TOTAL);
    dag_gemm_kernel<<<NCTA, NTHREADS, SMEM_TOTAL>>>(X, (float*)d_out);
}

// round 7
// speedup vs baseline: 1.2986x; 1.2986x over previous
#include <cuda_runtime.h>
#include <cstdint>

// ============================================================================
// Y[500000,256] = X @ W via mma.sync tf32 (tcgen05 unavailable at plain sm_103
// PTX target). Single fused kernel: each CTA zeroes + scatters its W-half
// directly into smem fragment order, then runs a persistent GEMM.
//
// R6 changes vs 772us best:
//  - A-fragment smem layout [mt][ks][reg][lane] (lane stride 4B):
//    producer stores become conflict-free STS.128 (was 8-way conflicted
//    sts32), consumer becomes conflict-free LDS.32x4. Crossbar cyc/chunk
//    for STS: ~2048 -> 256.
//  - Single kernel launch (W built in smem from w/rows/cols) so ncu profiles
//    the GEMM, and the g_Wt global roundtrip disappears.
//  - Back to the measured-best 256-thread / 8-warp 4mx2n config.
// ============================================================================

#define D_DIM    256
#define N_HALF   128
#define M_TILE   128
#define K_CHUNK  64
#define NCHUNKS  4
#define NROWS_T  500000L
#define NTILES_T 3907        // ceil(500000/128)
#define NPAIRS   76
#define NCTA     152
#define NTHREADS 256

// smem layout (bytes):
//  B frags [16 nt][32 ksg][32 lane][2 f32]                 = 131072
//  A frags 2 stages x [8 mt][8 ks][4 reg][32 lane] f32     = 65536
#define SB_B       0
#define SB_A       131072
#define A_STAGE_B  32768
#define SMEM_TOTAL (SB_A + 2 * A_STAGE_B)   // 196608

// ---------------------------------------------------------------------------
__device__ __forceinline__ uint32_t smem_u32(const void* p) {
    uint32_t a;
    asm("{ .reg .u64 t; cvta.to.shared.u64 t, %1; cvt.u32.u64 %0, t; }"
        : "=r"(a) : "l"(p));
    return a;
}
__device__ __forceinline__ float to_tf32(float x) {
    float r; asm("cvt.rna.tf32.f32 %0, %1;" : "=f"(r) : "f"(x)); return r;
}
__device__ __forceinline__ void sts32(uint32_t a, float v) {
    asm volatile("st.shared.f32 [%0], %1;" :: "r"(a), "f"(v) : "memory");
}
__device__ __forceinline__ void sts128(uint32_t a, float x, float y, float z, float w) {
    asm volatile("st.shared.v4.f32 [%0], {%1,%2,%3,%4};"
                 :: "r"(a), "f"(x), "f"(y), "f"(z), "f"(w) : "memory");
}
__device__ __forceinline__ uint32_t lds32(uint32_t a) {
    uint32_t v;
    asm volatile("ld.shared.b32 %0, [%1];" : "=r"(v) : "r"(a));
    return v;
}
__device__ __forceinline__ uint2 lds64(uint32_t a) {
    uint2 v;
    asm volatile("ld.shared.v2.b32 {%0,%1}, [%2];" : "=r"(v.x), "=r"(v.y) : "r"(a));
    return v;
}
__device__ __forceinline__ void stg64_cs(float* p, float a, float b) {
    asm volatile("st.global.cs.v2.f32 [%0], {%1,%2};"
                 :: "l"(p), "f"(a), "f"(b) : "memory");
}
// D = A(16x8,row) * B(8x8,col) + D, tf32 inputs (pre-rounded), f32 accum
__device__ __forceinline__ void mma_tf32(float* c, uint4 a, uint2 b) {
    asm volatile(
        "mma.sync.aligned.m16n8k8.row.col.f32.tf32.tf32.f32 "
        "{%0,%1,%2,%3}, {%4,%5,%6,%7}, {%8,%9}, {%0,%1,%2,%3};"
        : "+f"(c[0]), "+f"(c[1]), "+f"(c[2]), "+f"(c[3])
        : "r"(a.x), "r"(a.y), "r"(a.z), "r"(a.w), "r"(b.x), "r"(b.y));
}

// ---------------------------------------------------------------------------
// Fused build + persistent GEMM
// ---------------------------------------------------------------------------
__global__ void __launch_bounds__(NTHREADS, 1)
dag_gemm_kernel(const float* __restrict__ X,
                const float* __restrict__ wv,
                const int* __restrict__ rows,
                const int* __restrict__ cols,
                int nnz,
                float* __restrict__ Y) {
    extern __shared__ char smem[];
    const uint32_t sb = smem_u32(smem);
    const int tid  = threadIdx.x;
    const int w    = tid >> 5;
    const int lane = tid & 31;
    const int g    = lane >> 2;      // groupID
    const int tig  = lane & 3;       // thread-in-group
    const int cta  = blockIdx.x;
    const int h    = cta & 1;        // N-half
    const int pair = cta >> 1;
    const int ntiles = (NTILES_T - pair + NPAIRS - 1) / NPAIRS;

    // ---- build B-half fragments in smem: zero, then scatter -------------
    // B_frag[nt(16)][ksg(32)][lane(32)][j(2)] f32:
    //   value W[k][n]: n = h*128 + nt*8 + (lane>>2), k = ksg*8 + (lane&3) + j*4
    #pragma unroll
    for (int i = 0; i < 32; i++)
        sts128(sb + SB_B + (uint32_t)(tid + (i << 8)) * 16, 0.f, 0.f, 0.f, 0.f);
    __syncthreads();
    for (int i = tid; i < nnz; i += NTHREADS) {
        int nl = cols[i] - h * N_HALF;
        if ((unsigned)nl < (unsigned)N_HALF) {
            int k   = rows[i];
            int nt  = nl >> 3;
            int ln  = ((nl & 7) << 2) | (k & 3);
            int ksg = k >> 3;
            int j   = (k >> 2) & 1;
            uint32_t a = sb + SB_B + (uint32_t)(((nt * 32 + ksg) * 32 + ln) * 8 + j * 4);
            sts32(a, to_tf32(wv[i]));
        }
    }

    // producer mapping: row r = tid>>1, col half hc = tid&1 (32 cols each)
    const int pr  = tid >> 1;
    const int hc  = tid & 1;
    const int nchunks = ntiles * NCHUNKS;

    // warp tiling: 4 m-groups x 2 n-groups, warp tile 32x64
    const int mtg0 = (w & 3) * 2;           // first of 2 mtiles (of 8)
    const int ng   = (w >> 2);              // 0..1
    float acc[2][8][4];
    #pragma unroll
    for (int mt = 0; mt < 2; mt++)
        #pragma unroll
        for (int nt = 0; nt < 8; nt++)
            #pragma unroll
            for (int q = 0; q < 4; q++) acc[mt][nt][q] = 0.0f;

    // A-frag STS.128 addresses: layout [mt(8)][ks(8)][reg(4)][lane(32)] f32.
    // float4 q holds k0..k0+3 (k0 = hc*32+4q): same reg, lanes l0..l0+3.
    //   rl = pr&15, mt = pr>>4, ks = k0>>3, reg = (rl>>3)|(((k0>>2)&1)<<1),
    //   l0 = (rl&7)*4
    uint32_t a_sts[8];
    {
        int mt = pr >> 4, rl = pr & 15;
        #pragma unroll
        for (int q = 0; q < 8; q++) {
            int k0  = hc * 32 + q * 4;
            int reg = (rl >> 3) | (((k0 >> 2) & 1) << 1);
            int l0  = (rl & 7) << 2;
            a_sts[q] = (uint32_t)(((((mt * 8 + (k0 >> 3)) * 4 + reg) * 32) + l0) * 4);
        }
    }

    __syncthreads();   // B frags ready

    float4 v[8];
    // ---- prologue: load+convert+store chunk 0 ---------------------------
    {
        long m0 = (long)pair * M_TILE;
        long grow = m0 + pr;
        const float4* src = reinterpret_cast<const float4*>(
            X + grow * D_DIM + hc * 32);
        #pragma unroll
        for (int q = 0; q < 8; q++)
            v[q] = (grow < NROWS_T) ? src[q] : make_float4(0.f, 0.f, 0.f, 0.f);
        uint32_t ab = sb + SB_A;
        #pragma unroll
        for (int q = 0; q < 8; q++)
            sts128(ab + a_sts[q], to_tf32(v[q].x), to_tf32(v[q].y),
                                  to_tf32(v[q].z), to_tf32(v[q].w));
    }

    for (int cg = 0; cg < nchunks; cg++) {
        __syncthreads();   // chunk cg resident in buffer cg&1

        const int j  = cg >> 2;       // tile
        const int ch = cg & 3;        // k-chunk
        const long m0 = (long)(pair + (long)j * NPAIRS) * M_TILE;

        // prefetch next chunk into registers
        if (cg + 1 < nchunks) {
            const int jn  = (cg + 1) >> 2;
            const int chn = (cg + 1) & 3;
            long m0n = (long)(pair + (long)jn * NPAIRS) * M_TILE;
            long grow = m0n + pr;
            const float4* src = reinterpret_cast<const float4*>(
                X + grow * D_DIM + chn * K_CHUNK + hc * 32);
            #pragma unroll
            for (int q = 0; q < 8; q++)
                v[q] = (grow < NROWS_T) ? src[q] : make_float4(0.f, 0.f, 0.f, 0.f);
        }

        // ---- compute chunk from smem buffer -----------------------------
        {
            const uint32_t ab = sb + SB_A + (uint32_t)(cg & 1) * A_STAGE_B;
            const uint32_t bb = sb + SB_B;
            #pragma unroll
            for (int ks = 0; ks < 8; ks++) {
                const int ksg = ch * 8 + ks;
                uint4 a0, a1;
                {
                    uint32_t base0 = ab + (uint32_t)(((mtg0 * 8 + ks) * 4) * 128) + lane * 4;
                    a0.x = lds32(base0);
                    a0.y = lds32(base0 + 128);
                    a0.z = lds32(base0 + 256);
                    a0.w = lds32(base0 + 384);
                    uint32_t base1 = base0 + (uint32_t)(8 * 4 * 128);
                    a1.x = lds32(base1);
                    a1.y = lds32(base1 + 128);
                    a1.z = lds32(base1 + 256);
                    a1.w = lds32(base1 + 384);
                }
                uint2 bfr[8];
                #pragma unroll
                for (int nt = 0; nt < 8; nt++)
                    bfr[nt] = lds64(bb + (uint32_t)((((ng * 8 + nt) * 32 + ksg) * 32 + lane) * 8));
                #pragma unroll
                for (int nt = 0; nt < 8; nt++) {
                    mma_tf32(acc[0][nt], a0, bfr[nt]);
                    mma_tf32(acc[1][nt], a1, bfr[nt]);
                }
            }
        }

        // ---- epilogue on last chunk of tile -----------------------------
        if (ch == 3) {
            const long mw = m0 + (long)(w & 3) * 32;
            const int  nb = h * N_HALF + ng * 64;
            #pragma unroll
            for (int mt = 0; mt < 2; mt++) {
                long r0 = mw + mt * 16 + g;
                long r1 = r0 + 8;
                #pragma unroll
                for (int nt = 0; nt < 8; nt++) {
                    int c0 = nb + nt * 8 + tig * 2;
                    if (r0 < NROWS_T)
                        stg64_cs(Y + r0 * D_DIM + c0, acc[mt][nt][0], acc[mt][nt][1]);
                    if (r1 < NROWS_T)
                        stg64_cs(Y + r1 * D_DIM + c0, acc[mt][nt][2], acc[mt][nt][3]);
                    #pragma unroll
                    for (int q = 0; q < 4; q++) acc[mt][nt][q] = 0.0f;
                }
            }
        }

        // ---- convert + store prefetched chunk into other buffer ---------
        if (cg + 1 < nchunks) {
            uint32_t ab = sb + SB_A + (uint32_t)((cg + 1) & 1) * A_STAGE_B;
            #pragma unroll
            for (int q = 0; q < 8; q++)
                sts128(ab + a_sts[q], to_tf32(v[q].x), to_tf32(v[q].y),
                                      to_tf32(v[q].z), to_tf32(v[q].w));
        }
    }
}

// ---------------------------------------------------------------------------
extern "C" void kernel_launch(void* const* d_in, const int* in_sizes, int n_in,
                              void* d_out, int out_size) {
    const float* X    = (const float*)d_in[0];
    const float* wv   = (const float*)d_in[1];
    const int*   rows = (const int*)d_in[2];
    const int*   cols = (const int*)d_in[3];
    const int nnz = in_sizes[1];

    cudaFuncSetAttribute(dag_gemm_kernel,
                         cudaFuncAttributeMaxDynamicSharedMemorySize, SMEM_TOTAL);
    dag_gemm_kernel<<<NCTA, NTHREADS, SMEM_TOTAL>>>(X, wv, rows, cols, nnz,
                                                    (float*)d_out);
}